// round 12
// baseline (speedup 1.0000x reference)
#include <cuda_runtime.h>
#include <cuda_fp16.h>
#include <mma.h>
#include <math.h>

using namespace nvcuda;

#define NNODES 50000
#define MPAD   50176
#define EMAX   800000
#define E2MAX  (EMAX + NNODES)

// ---------------- device scratch ----------------
__device__ __align__(16) __half g_xph [NNODES * 256]; // fp16 features L1/L2 (4 heads x 64)
__device__ __align__(16) __half g_xph3[NNODES * 256]; // fp16 features L3 (4x40 padded to 4x64; pads stay 0)
__device__ __align__(16) __half g_hh [MPAD * 64];     // fp16 hidden activations (rows >= NNODES stay 0)
__device__ __align__(16) float  g_as [NNODES * 4];
__device__ __align__(16) float  g_ad [NNODES * 4];
__device__ unsigned g_gmax[12];
__device__ int   g_cnt[NNODES];        // invariant: zero at entry (reset by scan)
__device__ int   g_rowstart[NNODES + 1];
__device__ int   g_esrc[E2MAX];
__device__ int   g_epos[E2MAX];
__device__ __align__(16) __half g_bcat1h[128 * 320];
__device__ __align__(16) __half g_bcat2h[64  * 320];
__device__ __align__(16) __half g_bcat3h[64  * 192];

__device__ __forceinline__ unsigned fenc(float f) {
    unsigned u = __float_as_uint(f);
    return (u & 0x80000000u) ? ~u : (u | 0x80000000u);
}
__device__ __forceinline__ float fdec(unsigned u) {
    u = (u & 0x80000000u) ? (u & 0x7fffffffu) : ~u;
    return __uint_as_float(u);
}

// ---------------- CSR branch ----------------
__global__ void count_kernel(const int* __restrict__ ei, int E) {
    int e = blockIdx.x * blockDim.x + threadIdx.x;
    int e2 = E + NNODES;
    if (e >= e2) return;
    int dst = (e < E) ? ei[E + e] : (e - E);
    g_epos[e] = atomicAdd(&g_cnt[dst], 1);
}

#define SCHUNK ((NNODES + 1023) / 1024)
__global__ void scan_kernel() {
    __shared__ int wsum[32];
    int t = threadIdx.x;
    int lo = t * SCHUNK;
    int hi = min(lo + SCHUNK, NNODES);
    int sum = 0;
    for (int i = lo; i < hi; i++) sum += g_cnt[i];
    int lane = t & 31, w = t >> 5;
    int v = sum;
    #pragma unroll
    for (int o = 1; o < 32; o <<= 1) {
        int nv = __shfl_up_sync(0xffffffffu, v, o);
        if (lane >= o) v += nv;
    }
    if (lane == 31) wsum[w] = v;
    __syncthreads();
    if (w == 0) {
        int x = wsum[lane];
        #pragma unroll
        for (int o = 1; o < 32; o <<= 1) {
            int nv = __shfl_up_sync(0xffffffffu, x, o);
            if (lane >= o) x += nv;
        }
        wsum[lane] = x;
    }
    __syncthreads();
    int excl = v - sum + ((w > 0) ? wsum[w - 1] : 0);
    int run = excl;
    for (int i = lo; i < hi; i++) {
        int c = g_cnt[i];
        g_rowstart[i] = run;
        run += c;
        g_cnt[i] = 0;
    }
    if (hi == NNODES) g_rowstart[NNODES] = run;
}

__global__ void scatter_kernel(const int* __restrict__ ei, int E) {
    int e = blockIdx.x * blockDim.x + threadIdx.x;
    int e2 = E + NNODES;
    if (e >= e2) return;
    int src, dst;
    if (e < E) { src = ei[e]; dst = ei[E + e]; }
    else       { src = e - E; dst = src; }
    g_esrc[g_rowstart[dst] + g_epos[e]] = src;
}

// ---------------- GEMM branch pre: bcat1/2/3 | gmax reset ----------------
__device__ void bcat_fill(const float* __restrict__ W, const float* __restrict__ aw_s,
                          const float* __restrict__ aw_d, __half* __restrict__ bcat,
                          int K, int C, int NP, int idx) {
    int HC = 4 * C, Nc = HC + 8;
    if (idx >= K * NP) return;
    int k = idx / NP, j = idx - k * NP;
    float v = 0.f;
    if (j < HC) {
        v = W[k * HC + j];
    } else if (j < Nc) {
        int t = j - HC;
        int h = t & 3;
        const float* a = (t >= 4) ? aw_d : aw_s;
        float sum = 0.f;
        #pragma unroll 4
        for (int c = 0; c < C; c++) sum = fmaf(W[k * HC + h * C + c], a[h * C + c], sum);
        v = sum;
    }
    bcat[idx] = __float2half_rn(v);
}

#define NB_B1    ((128 * 320 + 255) / 256)
#define NB_B2    ((64 * 320 + 255) / 256)
#define NB_B3    ((64 * 192 + 255) / 256)

__global__ void pre_gemm_kernel(const float* __restrict__ W1, const float* __restrict__ as1, const float* __restrict__ ad1,
                                const float* __restrict__ W2, const float* __restrict__ as2, const float* __restrict__ ad2,
                                const float* __restrict__ W3, const float* __restrict__ as3, const float* __restrict__ ad3) {
    int b = blockIdx.x;
    int tid = threadIdx.x;
    if (b == 0 && tid < 12) g_gmax[tid] = 0u;
    if (b < NB_B1) { bcat_fill(W1, as1, ad1, g_bcat1h, 128, 64, 320, b * 256 + tid); return; }
    b -= NB_B1;
    if (b < NB_B2) { bcat_fill(W2, as2, ad2, g_bcat2h, 64, 64, 320, b * 256 + tid); return; }
    b -= NB_B2;
    bcat_fill(W3, as3, ad3, g_bcat3h, 64, 40, 192, b * 256 + tid);
}

// ---------------- HGEMM v3: 64x64 tile, whole-K smem staging; fp16 epilogue ----------------
template<int L>
__global__ __launch_bounds__(128) void hgemm_kernel(const float* __restrict__ xext) {
    constexpr int K  = (L == 1) ? 128 : 64;
    constexpr int C  = (L == 3) ? 40 : 64;
    constexpr int HC = 4 * C;
    constexpr int NP = (L == 3) ? 192 : 320;
    constexpr int KP = K + 8;
    constexpr int M  = NNODES;
    const __half* __restrict__ B = (L == 1) ? g_bcat1h : (L == 2) ? g_bcat2h : g_bcat3h;

    constexpr int ABYTES = 64 * KP * 2;
    constexpr int BBYTES = K * 72 * 2;
    constexpr int TOTB   = (ABYTES + BBYTES) > (64 * 68 * 4) ? (ABYTES + BBYTES) : (64 * 68 * 4);
    __shared__ __align__(32) char smbuf[TOTB];
    __half (*Ah)[KP] = reinterpret_cast<__half(*)[KP]>(smbuf);
    __half (*Bh)[72] = reinterpret_cast<__half(*)[72]>(smbuf + ABYTES);
    float  (*Cs)[68] = reinterpret_cast<float(*)[68]>(smbuf);
    __shared__ unsigned smax[4];

    int tid = threadIdx.x;
    int m0 = blockIdx.y * 64, n0 = blockIdx.x * 64;
    if (tid < 4) smax[tid] = 0u;

    // stage A (64 x K); layer 1 reads fp32 x and converts in-flight
    if constexpr (L == 1) {
        #pragma unroll
        for (int i = tid; i < 64 * 16; i += 128) {
            int r = i >> 4, c = (i & 15) * 8;
            int gm = m0 + r;
            float4 f0 = make_float4(0.f, 0.f, 0.f, 0.f), f1 = f0;
            if (gm < M) {
                const float4* p = reinterpret_cast<const float4*>(xext + (size_t)gm * 128 + c);
                f0 = p[0]; f1 = p[1];
            }
            union { uint4 u; __half2 h[4]; } cv;
            cv.h[0] = __floats2half2_rn(f0.x, f0.y);
            cv.h[1] = __floats2half2_rn(f0.z, f0.w);
            cv.h[2] = __floats2half2_rn(f1.x, f1.y);
            cv.h[3] = __floats2half2_rn(f1.z, f1.w);
            *reinterpret_cast<uint4*>(&Ah[r][c]) = cv.u;
        }
    } else {
        constexpr int AV = 64 * K / 8;
        #pragma unroll
        for (int i = tid; i < AV; i += 128) {
            int r = i / (K / 8), c = (i % (K / 8)) * 8;
            *reinterpret_cast<uint4*>(&Ah[r][c]) =
                *reinterpret_cast<const uint4*>(g_hh + (size_t)(m0 + r) * K + c);
        }
    }
    constexpr int BV = K * 8;
    for (int i = tid; i < BV; i += 128) {
        int r = i >> 3, c = (i & 7) * 8;
        *reinterpret_cast<uint4*>(&Bh[r][c]) =
            *reinterpret_cast<const uint4*>(B + (size_t)r * NP + n0 + c);
    }
    __syncthreads();

    int warp = tid >> 5, wm = warp >> 1, wn = warp & 1;
    wmma::fragment<wmma::accumulator, 16, 16, 16, float> acc[2][2];
    #pragma unroll
    for (int i = 0; i < 2; i++)
        #pragma unroll
        for (int j = 0; j < 2; j++) wmma::fill_fragment(acc[i][j], 0.f);

    #pragma unroll
    for (int k0 = 0; k0 < K; k0 += 16) {
        wmma::fragment<wmma::matrix_a, 16, 16, 16, __half, wmma::row_major> af[2];
        wmma::fragment<wmma::matrix_b, 16, 16, 16, __half, wmma::row_major> bf[2];
        #pragma unroll
        for (int j = 0; j < 2; j++)
            wmma::load_matrix_sync(bf[j], &Bh[k0][wn * 32 + j * 16], 72);
        #pragma unroll
        for (int i = 0; i < 2; i++)
            wmma::load_matrix_sync(af[i], &Ah[wm * 32 + i * 16][k0], KP);
        #pragma unroll
        for (int i = 0; i < 2; i++)
            #pragma unroll
            for (int j = 0; j < 2; j++)
                wmma::mma_sync(acc[i][j], af[i], bf[j], acc[i][j]);
    }
    __syncthreads();

    #pragma unroll
    for (int i = 0; i < 2; i++)
        #pragma unroll
        for (int j = 0; j < 2; j++)
            wmma::store_matrix_sync(&Cs[wm * 32 + i * 16][wn * 32 + j * 16],
                                    acc[i][j], 68, wmma::mem_row_major);
    __syncthreads();

    bool has_alpha = false;
    #pragma unroll
    for (int pass = 0; pass < 4; pass++) {
        int row   = (tid >> 3) + pass * 16;
        int chunk = tid & 7;
        int gm = m0 + row;
        if (gm >= M) continue;
        int col0 = n0 + chunk * 8;
        float v[8];
        #pragma unroll
        for (int k = 0; k < 8; k++) v[k] = Cs[row][chunk * 8 + k];
        if (col0 < HC) {
            union { uint4 u; __half2 h2[4]; } cv;
            cv.h2[0] = __floats2half2_rn(v[0], v[1]);
            cv.h2[1] = __floats2half2_rn(v[2], v[3]);
            cv.h2[2] = __floats2half2_rn(v[4], v[5]);
            cv.h2[3] = __floats2half2_rn(v[6], v[7]);
            if constexpr (L != 3) {
                *reinterpret_cast<uint4*>(g_xph + (size_t)gm * 256 + col0) = cv.u;
            } else {
                // head width 40 is a multiple of 8, so this 8-col chunk lies in one head
                int h = col0 / 40, c = col0 - h * 40;
                *reinterpret_cast<uint4*>(g_xph3 + (size_t)gm * 256 + h * 64 + c) = cv.u;
            }
        } else if (col0 == HC) {
            *reinterpret_cast<float4*>(g_as + gm * 4) = make_float4(v[0], v[1], v[2], v[3]);
            *reinterpret_cast<float4*>(g_ad + gm * 4) = make_float4(v[4], v[5], v[6], v[7]);
            #pragma unroll
            for (int k = 0; k < 4; k++) atomicMax(&smax[k], fenc(v[k]));
            has_alpha = true;
        }
    }
    __syncthreads();
    if (__syncthreads_or(has_alpha) && tid < 4)
        atomicMax(&g_gmax[(L - 1) * 4 + tid], smax[tid]);
}

// ---------------- aggregation v4: whole warp per edge, fp16 HFMA2, no converts ----------------
// lane = h*8 + q; lane covers halves [h*64 + q*8, +8) of the edge's 256-half row
template<int L, bool LOGSM, bool OUT_GH>
__global__ __launch_bounds__(256) void agg_kernel(const float* __restrict__ bias,
                                                  float* __restrict__ out_ext) {
    constexpr int C = (L == 3) ? 40 : 64;
    int warp = (blockIdx.x * blockDim.x + threadIdx.x) >> 5;
    if (warp >= NNODES) return;
    int lane = threadIdx.x & 31;
    int h = lane >> 3, q = lane & 7;
    int n = warp;

    const __half* __restrict__ xp = (L == 3) ? g_xph3 : g_xph;
    int loff = h * 64 + q * 8;     // in halves

    float adh = g_ad[n * 4 + h];
    float Mh  = fdec(g_gmax[(L - 1) * 4 + h]);
    float em  = Mh + adh;
    float stab = fmaxf(em, 0.2f * em);

    float s = 0.f;
    __half2 acc[4];
    #pragma unroll
    for (int k = 0; k < 4; k++) acc[k] = __float2half2_rn(0.f);

    #define EDGE_FMA(PH, QV)                                                                  \
        {                                                                                     \
            acc[0] = __hfma2(PH, *reinterpret_cast<const __half2*>(&QV.x), acc[0]);           \
            acc[1] = __hfma2(PH, *reinterpret_cast<const __half2*>(&QV.y), acc[1]);           \
            acc[2] = __hfma2(PH, *reinterpret_cast<const __half2*>(&QV.z), acc[2]);           \
            acc[3] = __hfma2(PH, *reinterpret_cast<const __half2*>(&QV.w), acc[3]);           \
        }
    // NOTE: uint4 fields are 4B; each holds one half2 pair... but we need 8 halves.
    // uint4 = 16B = 8 halves = 4 half2: x->h[0..1], y->h[2..3], z->h[4..5], w->h[6..7].
    // reinterpret of &QV.x as half2 gives halves 0..1 etc. Correct.

    int beg = g_rowstart[n], end = g_rowstart[n + 1];
    int base = beg;
    while (base < end) {
        int nload = min(32, end - base);
        int src_l = (lane < nload) ? g_esrc[base + lane] : 0;
        int j = 0;
        for (; j + 1 < nload; j += 2) {
            int s0 = __shfl_sync(0xffffffffu, src_l, j);
            int s1 = __shfl_sync(0xffffffffu, src_l, j + 1);
            float a0 = g_as[s0 * 4 + h] + adh;
            float a1 = g_as[s1 * 4 + h] + adh;
            uint4 q0 = *reinterpret_cast<const uint4*>(xp + (size_t)s0 * 256 + loff);
            uint4 q1 = *reinterpret_cast<const uint4*>(xp + (size_t)s1 * 256 + loff);
            a0 = fmaxf(a0, 0.2f * a0);
            a1 = fmaxf(a1, 0.2f * a1);
            float p0 = __expf(a0 - stab);
            float p1 = __expf(a1 - stab);
            s += p0 + p1;
            __half2 ph0 = __float2half2_rn(p0);
            __half2 ph1 = __float2half2_rn(p1);
            EDGE_FMA(ph0, q0);
            EDGE_FMA(ph1, q1);
        }
        if (j < nload) {
            int s0 = __shfl_sync(0xffffffffu, src_l, j);
            float a0 = g_as[s0 * 4 + h] + adh;
            uint4 q0 = *reinterpret_cast<const uint4*>(xp + (size_t)s0 * 256 + loff);
            a0 = fmaxf(a0, 0.2f * a0);
            float p0 = __expf(a0 - stab);
            s += p0;
            __half2 ph0 = __float2half2_rn(p0);
            EDGE_FMA(ph0, q0);
        }
        base += nload;
    }
    #undef EDGE_FMA

    // per-head normalize, then mean over heads (head groups at lane stride 8)
    float inv_s = 1.f / s;
    float r[8];
    #pragma unroll
    for (int k = 0; k < 4; k++) {
        float2 f = __half22float2(acc[k]);
        r[2 * k]     = f.x * inv_s;
        r[2 * k + 1] = f.y * inv_s;
    }
    #pragma unroll
    for (int k = 0; k < 8; k++) {
        r[k] += __shfl_xor_sync(0xffffffffu, r[k], 8);
        r[k] += __shfl_xor_sync(0xffffffffu, r[k], 16);
        int c = q * 8 + k;
        float bv = (c < C) ? bias[c] : 0.f;
        r[k] = fmaxf(0.25f * r[k] + bv, 0.f);   // bias + relu
    }
    if (LOGSM) {
        #pragma unroll
        for (int k = 0; k < 8; k++)
            if (q * 8 + k >= C) r[k] = -INFINITY;
        float lm = r[0];
        #pragma unroll
        for (int k = 1; k < 8; k++) lm = fmaxf(lm, r[k]);
        #pragma unroll
        for (int o = 1; o < 8; o <<= 1) lm = fmaxf(lm, __shfl_xor_sync(0xffffffffu, lm, o));
        float le = 0.f;
        #pragma unroll
        for (int k = 0; k < 8; k++) le += __expf(r[k] - lm);
        #pragma unroll
        for (int o = 1; o < 8; o <<= 1) le += __shfl_xor_sync(0xffffffffu, le, o);
        float lse = lm + __logf(le);
        #pragma unroll
        for (int k = 0; k < 8; k++) r[k] -= lse;
    }
    if (lane < 8) {                          // h == 0 group holds the head-mean
        if constexpr (OUT_GH) {
            union { uint4 u; __half2 h2[4]; } cv;
            cv.h2[0] = __floats2half2_rn(r[0], r[1]);
            cv.h2[1] = __floats2half2_rn(r[2], r[3]);
            cv.h2[2] = __floats2half2_rn(r[4], r[5]);
            cv.h2[3] = __floats2half2_rn(r[6], r[7]);
            *reinterpret_cast<uint4*>(g_hh + (size_t)n * 64 + q * 8) = cv.u;
        } else {
            if (q * 8 < C) {                 // q < 5 for C=40
                float* op = out_ext + (size_t)n * C + q * 8;
                *reinterpret_cast<float4*>(op)     = make_float4(r[0], r[1], r[2], r[3]);
                *reinterpret_cast<float4*>(op + 4) = make_float4(r[4], r[5], r[6], r[7]);
            }
        }
    }
}

// ---------------- host orchestration (fork-join; hgemm1 is submission #4 for ncu) ----------------
extern "C" void kernel_launch(void* const* d_in, const int* in_sizes, int n_in,
                              void* d_out, int out_size)
{
    const float* x   = (const float*)d_in[0];
    const int*   ei  = (const int*)d_in[1];
    const float* W1  = (const float*)d_in[2];
    const float* as1 = (const float*)d_in[3];
    const float* ad1 = (const float*)d_in[4];
    const float* b1  = (const float*)d_in[5];
    const float* W2  = (const float*)d_in[6];
    const float* as2 = (const float*)d_in[7];
    const float* ad2 = (const float*)d_in[8];
    const float* b2  = (const float*)d_in[9];
    const float* W3  = (const float*)d_in[10];
    const float* as3 = (const float*)d_in[11];
    const float* ad3 = (const float*)d_in[12];
    const float* b3  = (const float*)d_in[13];
    float* out = (float*)d_out;

    int E  = in_sizes[1] / 2;
    int e2 = E + NNODES;

    static cudaStream_t s2 = nullptr;
    static cudaEvent_t evF = nullptr, evC = nullptr;
    if (s2 == nullptr) {
        cudaStreamCreateWithFlags(&s2, cudaStreamNonBlocking);
        cudaEventCreateWithFlags(&evF, cudaEventDisableTiming);
        cudaEventCreateWithFlags(&evC, cudaEventDisableTiming);
    }

    const int PG       = NB_B1 + NB_B2 + NB_B3;
    const int AGG_GRID = (NNODES + 7) / 8;
    const int MGRID    = (NNODES + 63) / 64;

    cudaEventRecord(evF, (cudaStream_t)0);
    cudaStreamWaitEvent(s2, evF, 0);

    pre_gemm_kernel<<<PG, 256>>>(W1, as1, ad1, W2, as2, ad2, W3, as3, ad3); // #1 (s0)
    count_kernel<<<(e2 + 255) / 256, 256, 0, s2>>>(ei, E);                  // #2 (s2)
    scan_kernel<<<1, 1024, 0, s2>>>();                                      // #3 (s2)
    hgemm_kernel<1><<<dim3(5, MGRID), 128>>>(x);                            // #4 (s0) <- profiled
    scatter_kernel<<<(e2 + 255) / 256, 256, 0, s2>>>(ei, E);                // #5 (s2)
    cudaEventRecord(evC, s2);

    cudaStreamWaitEvent((cudaStream_t)0, evC, 0);
    agg_kernel<1, false, true><<<AGG_GRID, 256>>>(b1, out);                 // #6

    hgemm_kernel<2><<<dim3(5, MGRID), 128>>>(nullptr);                      // #7
    agg_kernel<2, false, true><<<AGG_GRID, 256>>>(b2, out);                 // #8

    hgemm_kernel<3><<<dim3(3, MGRID), 128>>>(nullptr);                      // #9
    agg_kernel<3, true, false><<<AGG_GRID, 256>>>(b3, out);                 // #10
}

// round 13
// speedup vs baseline: 1.5868x; 1.5868x over previous
#include <cuda_runtime.h>
#include <cuda_fp16.h>
#include <cuda_fp8.h>
#include <mma.h>
#include <math.h>

using namespace nvcuda;

#define NNODES 50000
#define MPAD   50176
#define EMAX   800000
#define E2MAX  (EMAX + NNODES)

// ---------------- device scratch ----------------
__device__ __align__(16) unsigned char g_xpq [NNODES * 256]; // fp8 features L1/L2 (4 heads x 64)
__device__ __align__(16) unsigned char g_xpq3[NNODES * 256]; // fp8 features L3 (4x40 padded to 4x64; pads stay 0)
__device__ __align__(16) __half g_hh [MPAD * 64];     // fp16 hidden activations (rows >= NNODES stay 0)
__device__ __align__(16) float  g_as [NNODES * 4];
__device__ __align__(16) float  g_ad [NNODES * 4];
__device__ unsigned g_gmax[12];
__device__ int   g_cnt[NNODES];        // invariant: zero at entry (reset by scan)
__device__ int   g_rowstart[NNODES + 1];
__device__ int   g_esrc[E2MAX];
__device__ int   g_epos[E2MAX];
__device__ __align__(16) __half g_bcat1h[128 * 320];
__device__ __align__(16) __half g_bcat2h[64  * 320];
__device__ __align__(16) __half g_bcat3h[64  * 192];

__device__ __forceinline__ unsigned fenc(float f) {
    unsigned u = __float_as_uint(f);
    return (u & 0x80000000u) ? ~u : (u | 0x80000000u);
}
__device__ __forceinline__ float fdec(unsigned u) {
    u = (u & 0x80000000u) ? (u & 0x7fffffffu) : ~u;
    return __uint_as_float(u);
}
__device__ __forceinline__ __half2 cvt_fp8x2(unsigned short u) {
    __half2_raw r = __nv_cvt_fp8x2_to_halfraw2((__nv_fp8x2_storage_t)u, __NV_E4M3);
    return *reinterpret_cast<__half2*>(&r);
}

// ---------------- CSR branch ----------------
__global__ void count_kernel(const int* __restrict__ ei, int E) {
    int e = blockIdx.x * blockDim.x + threadIdx.x;
    int e2 = E + NNODES;
    if (e >= e2) return;
    int dst = (e < E) ? ei[E + e] : (e - E);
    g_epos[e] = atomicAdd(&g_cnt[dst], 1);
}

#define SCHUNK ((NNODES + 1023) / 1024)
__global__ void scan_kernel() {
    __shared__ int wsum[32];
    int t = threadIdx.x;
    int lo = t * SCHUNK;
    int hi = min(lo + SCHUNK, NNODES);
    int sum = 0;
    for (int i = lo; i < hi; i++) sum += g_cnt[i];
    int lane = t & 31, w = t >> 5;
    int v = sum;
    #pragma unroll
    for (int o = 1; o < 32; o <<= 1) {
        int nv = __shfl_up_sync(0xffffffffu, v, o);
        if (lane >= o) v += nv;
    }
    if (lane == 31) wsum[w] = v;
    __syncthreads();
    if (w == 0) {
        int x = wsum[lane];
        #pragma unroll
        for (int o = 1; o < 32; o <<= 1) {
            int nv = __shfl_up_sync(0xffffffffu, x, o);
            if (lane >= o) x += nv;
        }
        wsum[lane] = x;
    }
    __syncthreads();
    int excl = v - sum + ((w > 0) ? wsum[w - 1] : 0);
    int run = excl;
    for (int i = lo; i < hi; i++) {
        int c = g_cnt[i];
        g_rowstart[i] = run;
        run += c;
        g_cnt[i] = 0;
    }
    if (hi == NNODES) g_rowstart[NNODES] = run;
}

__global__ void scatter_kernel(const int* __restrict__ ei, int E) {
    int e = blockIdx.x * blockDim.x + threadIdx.x;
    int e2 = E + NNODES;
    if (e >= e2) return;
    int src, dst;
    if (e < E) { src = ei[e]; dst = ei[E + e]; }
    else       { src = e - E; dst = src; }
    g_esrc[g_rowstart[dst] + g_epos[e]] = src;
}

// ---------------- GEMM branch pre: bcat1/2/3 | gmax reset ----------------
__device__ void bcat_fill(const float* __restrict__ W, const float* __restrict__ aw_s,
                          const float* __restrict__ aw_d, __half* __restrict__ bcat,
                          int K, int C, int NP, int idx) {
    int HC = 4 * C, Nc = HC + 8;
    if (idx >= K * NP) return;
    int k = idx / NP, j = idx - k * NP;
    float v = 0.f;
    if (j < HC) {
        v = W[k * HC + j];
    } else if (j < Nc) {
        int t = j - HC;
        int h = t & 3;
        const float* a = (t >= 4) ? aw_d : aw_s;
        float sum = 0.f;
        #pragma unroll 4
        for (int c = 0; c < C; c++) sum = fmaf(W[k * HC + h * C + c], a[h * C + c], sum);
        v = sum;
    }
    bcat[idx] = __float2half_rn(v);
}

#define NB_B1    ((128 * 320 + 255) / 256)
#define NB_B2    ((64 * 320 + 255) / 256)
#define NB_B3    ((64 * 192 + 255) / 256)

__global__ void pre_gemm_kernel(const float* __restrict__ W1, const float* __restrict__ as1, const float* __restrict__ ad1,
                                const float* __restrict__ W2, const float* __restrict__ as2, const float* __restrict__ ad2,
                                const float* __restrict__ W3, const float* __restrict__ as3, const float* __restrict__ ad3) {
    int b = blockIdx.x;
    int tid = threadIdx.x;
    if (b == 0 && tid < 12) g_gmax[tid] = 0u;   // ordered before hgemm atomicMax (same stream)
    if (b < NB_B1) { bcat_fill(W1, as1, ad1, g_bcat1h, 128, 64, 320, b * 256 + tid); return; }
    b -= NB_B1;
    if (b < NB_B2) { bcat_fill(W2, as2, ad2, g_bcat2h, 64, 64, 320, b * 256 + tid); return; }
    b -= NB_B2;
    bcat_fill(W3, as3, ad3, g_bcat3h, 64, 40, 192, b * 256 + tid);
}

// ---------------- HGEMM v4: 64x64 tile, 256 threads (4x2 warps, 16x32 warp tile) ----------------
template<int L>
__global__ __launch_bounds__(256) void hgemm_kernel(const float* __restrict__ xext) {
    constexpr int K  = (L == 1) ? 128 : 64;
    constexpr int C  = (L == 3) ? 40 : 64;
    constexpr int HC = 4 * C;
    constexpr int NP = (L == 3) ? 192 : 320;
    constexpr int KP = K + 8;
    constexpr int M  = NNODES;
    const __half* __restrict__ B = (L == 1) ? g_bcat1h : (L == 2) ? g_bcat2h : g_bcat3h;

    constexpr int ABYTES = 64 * KP * 2;
    constexpr int BBYTES = K * 72 * 2;
    constexpr int TOTB   = (ABYTES + BBYTES) > (64 * 68 * 4) ? (ABYTES + BBYTES) : (64 * 68 * 4);
    __shared__ __align__(32) char smbuf[TOTB];
    __half (*Ah)[KP] = reinterpret_cast<__half(*)[KP]>(smbuf);
    __half (*Bh)[72] = reinterpret_cast<__half(*)[72]>(smbuf + ABYTES);
    float  (*Cs)[68] = reinterpret_cast<float(*)[68]>(smbuf);
    __shared__ unsigned smax[4];

    int tid = threadIdx.x;
    int m0 = blockIdx.y * 64, n0 = blockIdx.x * 64;
    if (tid < 4) smax[tid] = 0u;

    // stage A (64 x K); layer 1 reads fp32 x and converts in-flight
    if constexpr (L == 1) {
        #pragma unroll
        for (int i = tid; i < 64 * 16; i += 256) {
            int r = i >> 4, c = (i & 15) * 8;
            int gm = m0 + r;
            float4 f0 = make_float4(0.f, 0.f, 0.f, 0.f), f1 = f0;
            if (gm < M) {
                const float4* p = reinterpret_cast<const float4*>(xext + (size_t)gm * 128 + c);
                f0 = p[0]; f1 = p[1];
            }
            union { uint4 u; __half2 h[4]; } cv;
            cv.h[0] = __floats2half2_rn(f0.x, f0.y);
            cv.h[1] = __floats2half2_rn(f0.z, f0.w);
            cv.h[2] = __floats2half2_rn(f1.x, f1.y);
            cv.h[3] = __floats2half2_rn(f1.z, f1.w);
            *reinterpret_cast<uint4*>(&Ah[r][c]) = cv.u;
        }
    } else {
        constexpr int AV = 64 * K / 8;
        #pragma unroll
        for (int i = tid; i < AV; i += 256) {
            int r = i / (K / 8), c = (i % (K / 8)) * 8;
            *reinterpret_cast<uint4*>(&Ah[r][c]) =
                *reinterpret_cast<const uint4*>(g_hh + (size_t)(m0 + r) * K + c);
        }
    }
    constexpr int BV = K * 8;
    #pragma unroll
    for (int i = tid; i < BV; i += 256) {
        int r = i >> 3, c = (i & 7) * 8;
        *reinterpret_cast<uint4*>(&Bh[r][c]) =
            *reinterpret_cast<const uint4*>(B + (size_t)r * NP + n0 + c);
    }
    __syncthreads();

    int warp = tid >> 5, wm = warp >> 1, wn = warp & 1;   // 4 x 2 warp grid
    wmma::fragment<wmma::accumulator, 16, 16, 16, float> acc[2];
    #pragma unroll
    for (int j = 0; j < 2; j++) wmma::fill_fragment(acc[j], 0.f);

    #pragma unroll
    for (int k0 = 0; k0 < K; k0 += 16) {
        wmma::fragment<wmma::matrix_a, 16, 16, 16, __half, wmma::row_major> af;
        wmma::fragment<wmma::matrix_b, 16, 16, 16, __half, wmma::row_major> bf[2];
        #pragma unroll
        for (int j = 0; j < 2; j++)
            wmma::load_matrix_sync(bf[j], &Bh[k0][wn * 32 + j * 16], 72);
        wmma::load_matrix_sync(af, &Ah[wm * 16][k0], KP);
        #pragma unroll
        for (int j = 0; j < 2; j++)
            wmma::mma_sync(acc[j], af, bf[j], acc[j]);
    }
    __syncthreads();   // A/B dead; Cs aliases them

    #pragma unroll
    for (int j = 0; j < 2; j++)
        wmma::store_matrix_sync(&Cs[wm * 16][wn * 32 + j * 16], acc[j], 68, wmma::mem_row_major);
    __syncthreads();

    bool has_alpha = false;
    #pragma unroll
    for (int pass = 0; pass < 2; pass++) {
        int row   = (tid >> 3) + pass * 32;
        int chunk = tid & 7;
        int gm = m0 + row;
        if (gm >= M) continue;
        int col0 = n0 + chunk * 8;
        float v[8];
        #pragma unroll
        for (int k = 0; k < 8; k++) v[k] = Cs[row][chunk * 8 + k];
        if (col0 < HC) {
            unsigned char bq[8];
            #pragma unroll
            for (int k = 0; k < 8; k++)
                bq[k] = (unsigned char)__nv_cvt_float_to_fp8(v[k], __NV_SATFINITE, __NV_E4M3);
            if constexpr (L != 3) {
                uint2 pk;
                pk.x = (unsigned)bq[0] | ((unsigned)bq[1] << 8) | ((unsigned)bq[2] << 16) | ((unsigned)bq[3] << 24);
                pk.y = (unsigned)bq[4] | ((unsigned)bq[5] << 8) | ((unsigned)bq[6] << 16) | ((unsigned)bq[7] << 24);
                *reinterpret_cast<uint2*>(g_xpq + (size_t)gm * 256 + col0) = pk;
            } else {
                #pragma unroll
                for (int k = 0; k < 8; k++) {
                    int j = col0 + k;
                    int h = j / 40, c = j - h * 40;
                    g_xpq3[(size_t)gm * 256 + h * 64 + c] = bq[k];
                }
            }
        } else if (col0 == HC) {
            *reinterpret_cast<float4*>(g_as + gm * 4) = make_float4(v[0], v[1], v[2], v[3]);
            *reinterpret_cast<float4*>(g_ad + gm * 4) = make_float4(v[4], v[5], v[6], v[7]);
            #pragma unroll
            for (int k = 0; k < 4; k++) atomicMax(&smax[k], fenc(v[k]));
            has_alpha = true;
        }
    }
    __syncthreads();
    if (__syncthreads_or(has_alpha) && tid < 4)
        atomicMax(&g_gmax[(L - 1) * 4 + tid], smax[tid]);
}

// ---------------- aggregation v3 (R11, proven): src prefetch + 2 edges per LDG, fp8 ----------------
template<int L, bool LOGSM, bool OUT_GH>
__global__ __launch_bounds__(256) void agg_kernel(const float* __restrict__ bias,
                                                  float* __restrict__ out_ext) {
    constexpr int C = (L == 3) ? 40 : 64;
    int warp = (blockIdx.x * blockDim.x + threadIdx.x) >> 5;
    if (warp >= NNODES) return;
    int lane = threadIdx.x & 31;
    int half = lane >> 4;
    int l = lane & 15;
    int h = l >> 2, q = l & 3;
    int n = warp;

    const unsigned char* __restrict__ xq = (L == 3) ? g_xpq3 : g_xpq;
    size_t loff = (size_t)h * 64 + q * 16;

    float adh = g_ad[n * 4 + h];
    float Mh  = fdec(g_gmax[(L - 1) * 4 + h]);
    float em  = Mh + adh;
    float stab = fmaxf(em, 0.2f * em);

    float s = 0.f;
    __half2 acc[8];
    #pragma unroll
    for (int k = 0; k < 8; k++) acc[k] = __float2half2_rn(0.f);

    #define EDGE_FMA(P, QV)                                                     \
        {                                                                       \
            __half2 ph = __float2half2_rn(P);                                   \
            acc[0] = __hfma2(ph, cvt_fp8x2((unsigned short)(QV.x)),       acc[0]); \
            acc[1] = __hfma2(ph, cvt_fp8x2((unsigned short)(QV.x >> 16)), acc[1]); \
            acc[2] = __hfma2(ph, cvt_fp8x2((unsigned short)(QV.y)),       acc[2]); \
            acc[3] = __hfma2(ph, cvt_fp8x2((unsigned short)(QV.y >> 16)), acc[3]); \
            acc[4] = __hfma2(ph, cvt_fp8x2((unsigned short)(QV.z)),       acc[4]); \
            acc[5] = __hfma2(ph, cvt_fp8x2((unsigned short)(QV.z >> 16)), acc[5]); \
            acc[6] = __hfma2(ph, cvt_fp8x2((unsigned short)(QV.w)),       acc[6]); \
            acc[7] = __hfma2(ph, cvt_fp8x2((unsigned short)(QV.w >> 16)), acc[7]); \
        }

    int beg = g_rowstart[n], end = g_rowstart[n + 1];
    int base = beg;
    while (base < end) {
        int nload = min(32, end - base);
        int src_l = (lane < nload) ? g_esrc[base + lane] : 0;
        int j = 0;
        for (; j + 3 < nload; j += 4) {
            int sA = __shfl_sync(0xffffffffu, src_l, j + half);
            int sB = __shfl_sync(0xffffffffu, src_l, j + 2 + half);
            float aA = g_as[sA * 4 + h] + adh;
            float aB = g_as[sB * 4 + h] + adh;
            uint4 qA = *reinterpret_cast<const uint4*>(xq + (size_t)sA * 256 + loff);
            uint4 qB = *reinterpret_cast<const uint4*>(xq + (size_t)sB * 256 + loff);
            aA = fmaxf(aA, 0.2f * aA);
            aB = fmaxf(aB, 0.2f * aB);
            float pA = __expf(aA - stab);
            float pB = __expf(aB - stab);
            s += pA + pB;
            EDGE_FMA(pA, qA);
            EDGE_FMA(pB, qB);
        }
        for (; j < nload; j += 2) {
            int kk = j + half;
            bool valid = kk < nload;
            int sA = __shfl_sync(0xffffffffu, src_l, valid ? kk : 0);
            float aA = valid ? (g_as[sA * 4 + h] + adh) : -1e30f;
            uint4 qA = *reinterpret_cast<const uint4*>(xq + (size_t)sA * 256 + loff);
            aA = fmaxf(aA, 0.2f * aA);
            float pA = __expf(aA - stab);
            s += pA;
            EDGE_FMA(pA, qA);
        }
        base += nload;
    }
    #undef EDGE_FMA

    // merge the two edge halves
    #pragma unroll
    for (int k = 0; k < 8; k++) {
        unsigned u = *reinterpret_cast<unsigned*>(&acc[k]);
        unsigned o = __shfl_xor_sync(0xffffffffu, u, 16);
        acc[k] = __hadd2(acc[k], *reinterpret_cast<__half2*>(&o));
    }
    s += __shfl_xor_sync(0xffffffffu, s, 16);

    float inv_s = 1.f / s;
    float r[16];
    #pragma unroll
    for (int k = 0; k < 8; k++) {
        float2 f = __half22float2(acc[k]);
        r[2 * k]     = f.x * inv_s;
        r[2 * k + 1] = f.y * inv_s;
    }
    #pragma unroll
    for (int k = 0; k < 16; k++) {
        r[k] += __shfl_xor_sync(0xffffffffu, r[k], 4);
        r[k] += __shfl_xor_sync(0xffffffffu, r[k], 8);
        int c = q * 16 + k;
        float bv = (c < C) ? bias[c] : 0.f;
        r[k] = fmaxf(0.25f * r[k] + bv, 0.f);
    }
    if (LOGSM) {
        #pragma unroll
        for (int k = 0; k < 16; k++)
            if (q * 16 + k >= C) r[k] = -INFINITY;
        float lm = r[0];
        #pragma unroll
        for (int k = 1; k < 16; k++) lm = fmaxf(lm, r[k]);
        lm = fmaxf(lm, __shfl_xor_sync(0xffffffffu, lm, 1));
        lm = fmaxf(lm, __shfl_xor_sync(0xffffffffu, lm, 2));
        float le = 0.f;
        #pragma unroll
        for (int k = 0; k < 16; k++) le += __expf(r[k] - lm);
        le += __shfl_xor_sync(0xffffffffu, le, 1);
        le += __shfl_xor_sync(0xffffffffu, le, 2);
        float lse = lm + __logf(le);
        #pragma unroll
        for (int k = 0; k < 16; k++) r[k] -= lse;
    }
    if (lane < 4) {
        if constexpr (OUT_GH) {
            union { uint4 u[2]; __half2 h2[8]; } cv;
            #pragma unroll
            for (int k = 0; k < 8; k++) cv.h2[k] = __floats2half2_rn(r[2 * k], r[2 * k + 1]);
            uint4* dst = reinterpret_cast<uint4*>(g_hh + (size_t)n * 64 + q * 16);
            dst[0] = cv.u[0];
            dst[1] = cv.u[1];
        } else {
            #pragma unroll
            for (int kk = 0; kk < 4; kk++) {
                int c0 = q * 16 + kk * 4;
                if (c0 < C)
                    *reinterpret_cast<float4*>(out_ext + (size_t)n * C + c0) =
                        make_float4(r[kk * 4], r[kk * 4 + 1], r[kk * 4 + 2], r[kk * 4 + 3]);
            }
        }
    }
}

// ---------------- host orchestration (fork-join; hgemm1 = 4th submission for ncu) ----------------
extern "C" void kernel_launch(void* const* d_in, const int* in_sizes, int n_in,
                              void* d_out, int out_size)
{
    const float* x   = (const float*)d_in[0];
    const int*   ei  = (const int*)d_in[1];
    const float* W1  = (const float*)d_in[2];
    const float* as1 = (const float*)d_in[3];
    const float* ad1 = (const float*)d_in[4];
    const float* b1  = (const float*)d_in[5];
    const float* W2  = (const float*)d_in[6];
    const float* as2 = (const float*)d_in[7];
    const float* ad2 = (const float*)d_in[8];
    const float* b2  = (const float*)d_in[9];
    const float* W3  = (const float*)d_in[10];
    const float* as3 = (const float*)d_in[11];
    const float* ad3 = (const float*)d_in[12];
    const float* b3  = (const float*)d_in[13];
    float* out = (float*)d_out;

    int E  = in_sizes[1] / 2;
    int e2 = E + NNODES;

    static cudaStream_t s2 = nullptr;
    static cudaEvent_t evF = nullptr, evC = nullptr;
    if (s2 == nullptr) {
        cudaStreamCreateWithFlags(&s2, cudaStreamNonBlocking);
        cudaEventCreateWithFlags(&evF, cudaEventDisableTiming);
        cudaEventCreateWithFlags(&evC, cudaEventDisableTiming);
    }

    const int PG       = NB_B1 + NB_B2 + NB_B3;
    const int AGG_GRID = (NNODES + 7) / 8;
    const int MGRID    = (NNODES + 63) / 64;

    cudaEventRecord(evF, (cudaStream_t)0);
    cudaStreamWaitEvent(s2, evF, 0);

    count_kernel<<<(e2 + 255) / 256, 256, 0, s2>>>(ei, E);                  // #1 (s2)
    scan_kernel<<<1, 1024, 0, s2>>>();                                      // #2 (s2)
    pre_gemm_kernel<<<PG, 256>>>(W1, as1, ad1, W2, as2, ad2, W3, as3, ad3); // #3 (s0)
    hgemm_kernel<1><<<dim3(5, MGRID), 256>>>(x);                            // #4 (s0) <- profiled
    scatter_kernel<<<(e2 + 255) / 256, 256, 0, s2>>>(ei, E);                // #5 (s2)
    cudaEventRecord(evC, s2);

    cudaStreamWaitEvent((cudaStream_t)0, evC, 0);
    agg_kernel<1, false, true><<<AGG_GRID, 256>>>(b1, out);                 // #6

    hgemm_kernel<2><<<dim3(5, MGRID), 256>>>(nullptr);                      // #7
    agg_kernel<2, false, true><<<AGG_GRID, 256>>>(b2, out);                 // #8

    hgemm_kernel<3><<<dim3(3, MGRID), 256>>>(nullptr);                      // #9
    agg_kernel<3, true, false><<<AGG_GRID, 256>>>(b3, out);                 // #10
}